// round 1
// baseline (speedup 1.0000x reference)
#include <cuda_runtime.h>
#include <math.h>

// NetVLAD: N=32 images, D=512 channels, S=1600 pixels, K=64 clusters.
// inputs: d_in[0]=x [N,D,S] f32, d_in[1]=W [K,D] f32, d_in[2]=centroids [K,D] f32
// output: [N, K*D] f32

#define NN 32
#define DDIM 512
#define SDIM 1600
#define KK 64

// scratch (no allocation allowed -> __device__ globals)
__device__ __align__(16) float g_a[NN * KK * SDIM];     // softmax * invn  (13.1 MB)
__device__ __align__(16) float g_agg[NN * KK * DDIM];   // agg             (4.2 MB)
__device__ float g_asum[NN * KK];
__device__ float g_gnorm[NN];

__global__ void k_zero() {
    int t = blockIdx.x * blockDim.x + threadIdx.x;
    if (t < NN * KK) g_asum[t] = 0.f;
    if (t < NN) g_gnorm[t] = 0.f;
}

// ---------------------------------------------------------------------------
// Kernel 1: logits GEMM (W[64,512] @ x[512, s-tile]) fused with:
//   - per-pixel sum-of-squares (computed while staging x tiles)
//   - scaling of logits by invn[s]
//   - softmax over k
//   - a_sum accumulation (plain softmax)
//   - write a' = softmax * invn[s] for the second GEMM
// grid: (25 s-tiles of 64, 32 n), 256 threads.
// ---------------------------------------------------------------------------
__global__ __launch_bounds__(256) void k_logits(const float* __restrict__ x,
                                                const float* __restrict__ W) {
    const int n = blockIdx.y;
    const int s0 = blockIdx.x * 64;
    const int tid = threadIdx.x;

    __shared__ __align__(16) float Wsh[32][68];   // [dd][k]
    __shared__ __align__(16) float Xsh[32][68];   // [dd][s]
    __shared__ float Lsh[64][65];                 // [s][k] logits -> exp
    __shared__ float ssp[256];
    __shared__ float sscale[64];                  // invn per pixel
    __shared__ float sinv[64];                    // 1/sum(exp) per pixel

    const int tk = (tid >> 4) << 2;   // k micro-tile base (0..60)
    const int ts = (tid & 15) << 2;   // s micro-tile base (0..60)

    float acc[4][4];
#pragma unroll
    for (int a = 0; a < 4; a++)
#pragma unroll
        for (int b = 0; b < 4; b++) acc[a][b] = 0.f;

    float myss = 0.f;   // partial sumsq for pixel s = tid & 63
    const float* xb = x + ((size_t)n * DDIM) * SDIM + s0;

    for (int dc = 0; dc < DDIM; dc += 32) {
#pragma unroll
        for (int i = 0; i < 8; i++) {
            int idx = tid + i * 256;
            int k = idx >> 5, dd = idx & 31;
            Wsh[dd][k] = W[k * DDIM + dc + dd];
        }
#pragma unroll
        for (int i = 0; i < 8; i++) {
            int idx = tid + i * 256;
            int dd = idx >> 6, s = idx & 63;           // s == tid & 63 (fixed per thread)
            float v = xb[(size_t)(dc + dd) * SDIM + s];
            Xsh[dd][s] = v;
            myss += v * v;
        }
        __syncthreads();
#pragma unroll
        for (int dd = 0; dd < 32; dd++) {
            float4 wv = *(const float4*)&Wsh[dd][tk];
            float4 xv = *(const float4*)&Xsh[dd][ts];
            float w[4] = {wv.x, wv.y, wv.z, wv.w};
            float xr[4] = {xv.x, xv.y, xv.z, xv.w};
#pragma unroll
            for (int a = 0; a < 4; a++)
#pragma unroll
                for (int b = 0; b < 4; b++) acc[a][b] += w[a] * xr[b];
        }
        __syncthreads();
    }

    // stash per-thread sumsq partial + raw logits
    ssp[tid] = myss;
#pragma unroll
    for (int a = 0; a < 4; a++)
#pragma unroll
        for (int b = 0; b < 4; b++) Lsh[ts + b][tk + a] = acc[a][b];
    __syncthreads();

    if (tid < 64) {
        float t = ssp[tid] + ssp[tid + 64] + ssp[tid + 128] + ssp[tid + 192];
        sscale[tid] = 1.f / fmaxf(sqrtf(t), 1e-12f);
    }
    __syncthreads();

    // softmax over k for each pixel (64 threads, one per pixel)
    if (tid < 64) {
        const int s = tid;
        const float sc = sscale[s];
        float m = -1e30f;
#pragma unroll
        for (int k = 0; k < 64; k++) m = fmaxf(m, Lsh[s][k] * sc);
        float sum = 0.f;
#pragma unroll
        for (int k = 0; k < 64; k++) {
            float e = expf(Lsh[s][k] * sc - m);
            Lsh[s][k] = e;
            sum += e;
        }
        sinv[s] = 1.f / sum;
    }
    __syncthreads();

    // a_sum: per k, sum of plain softmax over this pixel tile
    if (tid < 64) {
        const int k = tid;
        float t = 0.f;
#pragma unroll 8
        for (int s = 0; s < 64; s++) t += Lsh[s][k] * sinv[s];
        atomicAdd(&g_asum[n * KK + k], t);
    }
    // write a' = softmax * invn[s]  (coalesced over s)
    float* ab = g_a + (size_t)n * KK * SDIM + s0;
#pragma unroll
    for (int i = 0; i < 16; i++) {
        int idx = tid + i * 256;
        int k = idx >> 6, s = idx & 63;
        ab[(size_t)k * SDIM + s] = Lsh[s][k] * sinv[s] * sscale[s];
    }
}

// ---------------------------------------------------------------------------
// Kernel 2: agg[k,d] = sum_s a'[k,s] * x[d,s]   (contraction over contiguous s)
// grid: (8 d-tiles of 64, 32 n), 256 threads, 64x64 tile, 4x4 micro-tile.
// ---------------------------------------------------------------------------
__global__ __launch_bounds__(256) void k_agg(const float* __restrict__ x) {
    const int n = blockIdx.y;
    const int d0 = blockIdx.x * 64;
    const int tid = threadIdx.x;

    __shared__ __align__(16) float Ash[32][68];   // [ss][k]
    __shared__ __align__(16) float Xsh[32][68];   // [ss][d]

    const int tk = (tid >> 4) << 2;
    const int td = (tid & 15) << 2;

    float acc[4][4];
#pragma unroll
    for (int a = 0; a < 4; a++)
#pragma unroll
        for (int b = 0; b < 4; b++) acc[a][b] = 0.f;

    const float* xb = x + ((size_t)n * DDIM + d0) * SDIM;
    const float* ab = g_a + (size_t)n * KK * SDIM;

    for (int sc = 0; sc < SDIM; sc += 32) {
#pragma unroll
        for (int i = 0; i < 8; i++) {
            int idx = tid + i * 256;
            int k = idx >> 5, ss = idx & 31;
            Ash[ss][k] = ab[(size_t)k * SDIM + sc + ss];
        }
#pragma unroll
        for (int i = 0; i < 8; i++) {
            int idx = tid + i * 256;
            int d = idx >> 5, ss = idx & 31;
            Xsh[ss][d] = xb[(size_t)d * SDIM + sc + ss];
        }
        __syncthreads();
#pragma unroll
        for (int ss = 0; ss < 32; ss++) {
            float4 av = *(const float4*)&Ash[ss][tk];
            float4 xv = *(const float4*)&Xsh[ss][td];
            float aa[4] = {av.x, av.y, av.z, av.w};
            float xd[4] = {xv.x, xv.y, xv.z, xv.w};
#pragma unroll
            for (int a = 0; a < 4; a++)
#pragma unroll
                for (int b = 0; b < 4; b++) acc[a][b] += aa[a] * xd[b];
        }
        __syncthreads();
    }

#pragma unroll
    for (int a = 0; a < 4; a++) {
        float4 v = make_float4(acc[a][0], acc[a][1], acc[a][2], acc[a][3]);
        *(float4*)&g_agg[((size_t)(n * KK) + tk + a) * DDIM + d0 + td] = v;
    }
}

// ---------------------------------------------------------------------------
// Kernel 3: vlad = agg - a_sum*c ; intra-normalize over D ; write ; accumulate
// global sumsq per image.  grid: (64 k, 32 n), 128 threads (each 4 d via float4).
// ---------------------------------------------------------------------------
__global__ __launch_bounds__(128) void k_final1(const float* __restrict__ cent,
                                                float* __restrict__ out) {
    const int k = blockIdx.x, n = blockIdx.y;
    const int tid = threadIdx.x;
    const float as = g_asum[n * KK + k];

    float4 ag = *(const float4*)&g_agg[((size_t)(n * KK) + k) * DDIM + tid * 4];
    float4 c4 = *(const float4*)&cent[(size_t)k * DDIM + tid * 4];
    float vx = ag.x - as * c4.x;
    float vy = ag.y - as * c4.y;
    float vz = ag.z - as * c4.z;
    float vw = ag.w - as * c4.w;
    float ss = vx * vx + vy * vy + vz * vz + vw * vw;

#pragma unroll
    for (int o = 16; o > 0; o >>= 1) ss += __shfl_xor_sync(0xffffffffu, ss, o);
    __shared__ float wpart[4];
    if ((tid & 31) == 0) wpart[tid >> 5] = ss;
    __syncthreads();
    float tot = wpart[0] + wpart[1] + wpart[2] + wpart[3];

    float inv = 1.f / fmaxf(sqrtf(tot), 1e-12f);
    float4 o4 = make_float4(vx * inv, vy * inv, vz * inv, vw * inv);
    *(float4*)&out[(size_t)n * (KK * DDIM) + k * DDIM + tid * 4] = o4;

    if (tid == 0) atomicAdd(&g_gnorm[n], tot * inv * inv);
}

// Kernel 4: global L2 normalization per image.
__global__ __launch_bounds__(256) void k_final2(float* __restrict__ out) {
    int t = blockIdx.x * 256 + threadIdx.x;     // indexes float4; total 32*8192
    int n = t >> 13;                            // 8192 float4 per image
    float inv = 1.f / fmaxf(sqrtf(g_gnorm[n]), 1e-12f);
    float4 v = ((float4*)out)[t];
    v.x *= inv; v.y *= inv; v.z *= inv; v.w *= inv;
    ((float4*)out)[t] = v;
}

extern "C" void kernel_launch(void* const* d_in, const int* in_sizes, int n_in,
                              void* d_out, int out_size) {
    const float* x    = (const float*)d_in[0];
    const float* W    = (const float*)d_in[1];
    const float* cent = (const float*)d_in[2];
    float* out = (float*)d_out;

    k_zero<<<8, 256>>>();
    k_logits<<<dim3(25, 32), 256>>>(x, W);
    k_agg<<<dim3(8, 32), 256>>>(x);
    k_final1<<<dim3(64, 32), 128>>>(cent, out);
    k_final2<<<1024, 256>>>(out);
}

// round 6
// speedup vs baseline: 1.5636x; 1.5636x over previous
#include <cuda_runtime.h>
#include <cuda_bf16.h>
#include <math.h>

// NetVLAD: N=32, D=512, S=1600, K=64.
// d_in[0]=x [N,D,S] f32, d_in[1]=W [K,D] f32, d_in[2]=centroids [K,D] f32
// out: [N, K*D] f32

#define NN 32
#define DDIM 512
#define SDIM 1600
#define KK 64
#define NTILES 25   // s-tiles of 64

__device__ __align__(16) __nv_bfloat16 g_a[NN * KK * SDIM];  // softmax*invn (bf16)
__device__ __align__(16) float g_agg[NN * KK * DDIM];
__device__ __align__(16) float g_asum_part[NN * NTILES * KK];

__device__ __forceinline__ float to_tf32(float x) {
    float r;
    asm("cvt.rna.tf32.f32 %0, %1;" : "=f"(r) : "f"(x));
    return r;
}
__device__ __forceinline__ unsigned f2u(float x) { return __float_as_uint(x); }

__device__ __forceinline__ void mma_tf32(float* c, unsigned a0, unsigned a1,
                                         unsigned a2, unsigned a3,
                                         unsigned b0, unsigned b1) {
    asm volatile(
        "mma.sync.aligned.m16n8k8.row.col.f32.tf32.tf32.f32 "
        "{%0,%1,%2,%3},{%4,%5,%6,%7},{%8,%9},{%0,%1,%2,%3};\n"
        : "+f"(c[0]), "+f"(c[1]), "+f"(c[2]), "+f"(c[3])
        : "r"(a0), "r"(a1), "r"(a2), "r"(a3), "r"(b0), "r"(b1));
}

// ---------------------------------------------------------------------------
// Kernel 1: logits = W[64,512] @ x[512, 64 s] (tf32 mma) fused with per-pixel
// sumsq, softmax over k, a_sum partial, a' = softmax*invn -> bf16.
// grid (25, 32), 256 threads = 8 warps. Warp w owns k-rows [(w>>1)*16, +16)
// and s-columns [(w&1)*32, +32).
// ---------------------------------------------------------------------------
__global__ __launch_bounds__(256) void k_logits(const float* __restrict__ x,
                                                const float* __restrict__ W) {
    const int n = blockIdx.y;
    const int s0 = blockIdx.x * 64;
    const int tid = threadIdx.x;
    const int warp = tid >> 5, lane = tid & 31;
    const int gid = lane >> 2, tig = lane & 3;
    const int k0 = (warp >> 1) * 16;   // 0,16,32,48
    const int sh = (warp & 1) * 32;    // 0,32

    __shared__ __align__(16) float Wsh[64][36];   // [k][d32] tf32
    __shared__ __align__(16) float Xsh[32][72];   // [d32][s] tf32
    __shared__ float Lsh[64][65];                 // [k][s]
    __shared__ __align__(16) float ssp[32][64];
    __shared__ float sscale[64], sinv[64];

    float acc[4][4];
#pragma unroll
    for (int j = 0; j < 4; j++)
#pragma unroll
        for (int i = 0; i < 4; i++) acc[j][i] = 0.f;

    float ss[8];
#pragma unroll
    for (int i = 0; i < 8; i++) ss[i] = 0.f;

    const float* xb = x + (size_t)n * DDIM * SDIM + s0;
    const int wk = tid >> 2, wc = (tid & 3) * 8;    // W stage: row wk, cols wc..wc+7
    const int xd = tid >> 3, xs8 = (tid & 7) * 8;   // x stage: row xd, pix xs8..xs8+7

    for (int dc = 0; dc < DDIM; dc += 32) {
        float4 w0 = *(const float4*)&W[wk * DDIM + dc + wc];
        float4 w1 = *(const float4*)&W[wk * DDIM + dc + wc + 4];
        Wsh[wk][wc + 0] = to_tf32(w0.x); Wsh[wk][wc + 1] = to_tf32(w0.y);
        Wsh[wk][wc + 2] = to_tf32(w0.z); Wsh[wk][wc + 3] = to_tf32(w0.w);
        Wsh[wk][wc + 4] = to_tf32(w1.x); Wsh[wk][wc + 5] = to_tf32(w1.y);
        Wsh[wk][wc + 6] = to_tf32(w1.z); Wsh[wk][wc + 7] = to_tf32(w1.w);

        float4 x0 = *(const float4*)&xb[(size_t)(dc + xd) * SDIM + xs8];
        float4 x1 = *(const float4*)&xb[(size_t)(dc + xd) * SDIM + xs8 + 4];
        ss[0] += x0.x * x0.x; ss[1] += x0.y * x0.y;
        ss[2] += x0.z * x0.z; ss[3] += x0.w * x0.w;
        ss[4] += x1.x * x1.x; ss[5] += x1.y * x1.y;
        ss[6] += x1.z * x1.z; ss[7] += x1.w * x1.w;
        Xsh[xd][xs8 + 0] = to_tf32(x0.x); Xsh[xd][xs8 + 1] = to_tf32(x0.y);
        Xsh[xd][xs8 + 2] = to_tf32(x0.z); Xsh[xd][xs8 + 3] = to_tf32(x0.w);
        Xsh[xd][xs8 + 4] = to_tf32(x1.x); Xsh[xd][xs8 + 5] = to_tf32(x1.y);
        Xsh[xd][xs8 + 6] = to_tf32(x1.z); Xsh[xd][xs8 + 7] = to_tf32(x1.w);
        __syncthreads();

#pragma unroll
        for (int kk = 0; kk < 32; kk += 8) {
            unsigned a0 = f2u(Wsh[k0 + gid][kk + tig]);
            unsigned a1 = f2u(Wsh[k0 + gid + 8][kk + tig]);
            unsigned a2 = f2u(Wsh[k0 + gid][kk + tig + 4]);
            unsigned a3 = f2u(Wsh[k0 + gid + 8][kk + tig + 4]);
#pragma unroll
            for (int j = 0; j < 4; j++) {
                unsigned b0 = f2u(Xsh[kk + tig][sh + j * 8 + gid]);
                unsigned b1 = f2u(Xsh[kk + tig + 4][sh + j * 8 + gid]);
                mma_tf32(acc[j], a0, a1, a2, a3, b0, b1);
            }
        }
        __syncthreads();
    }

#pragma unroll
    for (int i = 0; i < 8; i++) ssp[xd][xs8 + i] = ss[i];
#pragma unroll
    for (int j = 0; j < 4; j++) {
        Lsh[k0 + gid][sh + j * 8 + 2 * tig]         = acc[j][0];
        Lsh[k0 + gid][sh + j * 8 + 2 * tig + 1]     = acc[j][1];
        Lsh[k0 + gid + 8][sh + j * 8 + 2 * tig]     = acc[j][2];
        Lsh[k0 + gid + 8][sh + j * 8 + 2 * tig + 1] = acc[j][3];
    }
    __syncthreads();

    if (tid < 64) {
        const int s = tid;
        float t = 0.f;
#pragma unroll
        for (int r = 0; r < 32; r++) t += ssp[r][s];
        const float sc = 1.f / fmaxf(sqrtf(t), 1e-12f);
        sscale[s] = sc;
        float m = -1e30f;
#pragma unroll
        for (int k = 0; k < 64; k++) m = fmaxf(m, Lsh[k][s] * sc);
        float sum = 0.f;
#pragma unroll
        for (int k = 0; k < 64; k++) {
            float e = expf(Lsh[k][s] * sc - m);
            Lsh[k][s] = e;
            sum += e;
        }
        sinv[s] = 1.f / sum;
    }
    __syncthreads();

    if (tid < 64) {
        const int k = tid;
        float t = 0.f;
#pragma unroll 8
        for (int s = 0; s < 64; s++) t += Lsh[k][s] * sinv[s];
        g_asum_part[((size_t)n * NTILES + blockIdx.x) * KK + k] = t;
    }

    __nv_bfloat16* ab = g_a + (size_t)n * KK * SDIM + s0;
#pragma unroll
    for (int i = 0; i < 16; i++) {
        int idx = tid + i * 256;
        int k = idx >> 6, s = idx & 63;
        ab[(size_t)k * SDIM + s] =
            __float2bfloat16(Lsh[k][s] * sinv[s] * sscale[s]);
    }
}

// ---------------------------------------------------------------------------
// Kernel 2: aggT[d,k] = sum_s x[d,s] * a'[k,s]  (tf32 mma; A=x rows=d, B=a').
// grid (8 d-tiles, 32 n), 256 threads = 8 warps. Warp w owns d-rows
// [(w>>1)*16, +16) and k-columns [(w&1)*32, +32).
// ---------------------------------------------------------------------------
__global__ __launch_bounds__(256) void k_agg(const float* __restrict__ x) {
    const int n = blockIdx.y;
    const int d0 = blockIdx.x * 64;
    const int tid = threadIdx.x;
    const int warp = tid >> 5, lane = tid & 31;
    const int gid = lane >> 2, tig = lane & 3;
    const int dw0 = (warp >> 1) * 16;   // 0,16,32,48
    const int kh = (warp & 1) * 32;     // 0,32

    __shared__ __align__(16) float Xsh[64][36];   // [d][s32] tf32
    __shared__ float Ash[32][66];                 // [s32][k]
    __shared__ __align__(16) float Tsh[64][68];   // [k][d]

    float acc[4][4];
#pragma unroll
    for (int j = 0; j < 4; j++)
#pragma unroll
        for (int i = 0; i < 4; i++) acc[j][i] = 0.f;

    const float* xb = x + (size_t)n * DDIM * SDIM + (size_t)d0 * SDIM;
    const __nv_bfloat16* ab = g_a + (size_t)n * KK * SDIM;
    const int ld = tid >> 2, ls8 = (tid & 3) * 8;   // row ld, 8 s values

    for (int sc = 0; sc < SDIM; sc += 32) {
        float4 x0 = *(const float4*)&xb[(size_t)ld * SDIM + sc + ls8];
        float4 x1 = *(const float4*)&xb[(size_t)ld * SDIM + sc + ls8 + 4];
        Xsh[ld][ls8 + 0] = to_tf32(x0.x); Xsh[ld][ls8 + 1] = to_tf32(x0.y);
        Xsh[ld][ls8 + 2] = to_tf32(x0.z); Xsh[ld][ls8 + 3] = to_tf32(x0.w);
        Xsh[ld][ls8 + 4] = to_tf32(x1.x); Xsh[ld][ls8 + 5] = to_tf32(x1.y);
        Xsh[ld][ls8 + 6] = to_tf32(x1.z); Xsh[ld][ls8 + 7] = to_tf32(x1.w);

        // a' tile: k=ld, s=sc+ls8..+7 -> transposed into Ash[s][k]
        uint4 u = *(const uint4*)&ab[(size_t)ld * SDIM + sc + ls8];
        __nv_bfloat162 p0 = *(__nv_bfloat162*)&u.x;
        __nv_bfloat162 p1 = *(__nv_bfloat162*)&u.y;
        __nv_bfloat162 p2 = *(__nv_bfloat162*)&u.z;
        __nv_bfloat162 p3 = *(__nv_bfloat162*)&u.w;
        Ash[ls8 + 0][ld] = __low2float(p0);  Ash[ls8 + 1][ld] = __high2float(p0);
        Ash[ls8 + 2][ld] = __low2float(p1);  Ash[ls8 + 3][ld] = __high2float(p1);
        Ash[ls8 + 4][ld] = __low2float(p2);  Ash[ls8 + 5][ld] = __high2float(p2);
        Ash[ls8 + 6][ld] = __low2float(p3);  Ash[ls8 + 7][ld] = __high2float(p3);
        __syncthreads();

#pragma unroll
        for (int kk = 0; kk < 32; kk += 8) {
            unsigned a0 = f2u(Xsh[dw0 + gid][kk + tig]);
            unsigned a1 = f2u(Xsh[dw0 + gid + 8][kk + tig]);
            unsigned a2 = f2u(Xsh[dw0 + gid][kk + tig + 4]);
            unsigned a3 = f2u(Xsh[dw0 + gid + 8][kk + tig + 4]);
#pragma unroll
            for (int j = 0; j < 4; j++) {
                unsigned b0 = f2u(Ash[kk + tig][kh + j * 8 + gid]);
                unsigned b1 = f2u(Ash[kk + tig + 4][kh + j * 8 + gid]);
                mma_tf32(acc[j], a0, a1, a2, a3, b0, b1);
            }
        }
        __syncthreads();
    }

    // C element (m = dw0+gid(+8), n = kh + j*8 + 2*tig(+1)) -> Tsh[k][d]
#pragma unroll
    for (int j = 0; j < 4; j++) {
        Tsh[kh + j * 8 + 2 * tig][dw0 + gid]         = acc[j][0];
        Tsh[kh + j * 8 + 2 * tig + 1][dw0 + gid]     = acc[j][1];
        Tsh[kh + j * 8 + 2 * tig][dw0 + gid + 8]     = acc[j][2];
        Tsh[kh + j * 8 + 2 * tig + 1][dw0 + gid + 8] = acc[j][3];
    }
    __syncthreads();
#pragma unroll
    for (int i = 0; i < 4; i++) {
        int idx = tid + i * 256;
        int k = idx >> 4, dd4 = (idx & 15) * 4;
        float4 v = *(const float4*)&Tsh[k][dd4];
        *(float4*)&g_agg[((size_t)n * KK + k) * DDIM + d0 + dd4] = v;
    }
}

// ---------------------------------------------------------------------------
// Kernel 3: a_sum reduce; vlad = agg - a_sum*c; intra-norm over D; *1/8
// (global norm of 64 unit-norm rows is exactly 8). grid (64,32), 128 thr.
// ---------------------------------------------------------------------------
__global__ __launch_bounds__(128) void k_final(const float* __restrict__ cent,
                                               float* __restrict__ out) {
    const int k = blockIdx.x, n = blockIdx.y;
    const int tid = threadIdx.x;

    __shared__ float s_as;
    __shared__ float wpart[4];

    if (tid < 32) {
        float p = (tid < NTILES)
                      ? g_asum_part[((size_t)n * NTILES + tid) * KK + k]
                      : 0.f;
#pragma unroll
        for (int o = 16; o > 0; o >>= 1) p += __shfl_xor_sync(0xffffffffu, p, o);
        if (tid == 0) s_as = p;
    }
    __syncthreads();
    const float as = s_as;

    float4 ag = *(const float4*)&g_agg[((size_t)n * KK + k) * DDIM + tid * 4];
    float4 c4 = *(const float4*)&cent[(size_t)k * DDIM + tid * 4];
    float vx = ag.x - as * c4.x;
    float vy = ag.y - as * c4.y;
    float vz = ag.z - as * c4.z;
    float vw = ag.w - as * c4.w;
    float ss = vx * vx + vy * vy + vz * vz + vw * vw;

#pragma unroll
    for (int o = 16; o > 0; o >>= 1) ss += __shfl_xor_sync(0xffffffffu, ss, o);
    if ((tid & 31) == 0) wpart[tid >> 5] = ss;
    __syncthreads();
    float tot = wpart[0] + wpart[1] + wpart[2] + wpart[3];

    const float inv = 0.125f / fmaxf(sqrtf(tot), 1e-12f);
    float4 o4 = make_float4(vx * inv, vy * inv, vz * inv, vw * inv);
    *(float4*)&out[(size_t)n * (KK * DDIM) + (size_t)k * DDIM + tid * 4] = o4;
}

extern "C" void kernel_launch(void* const* d_in, const int* in_sizes, int n_in,
                              void* d_out, int out_size) {
    const float* x    = (const float*)d_in[0];
    const float* W    = (const float*)d_in[1];
    const float* cent = (const float*)d_in[2];
    float* out = (float*)d_out;

    k_logits<<<dim3(NTILES, NN), 256>>>(x, W);
    k_agg<<<dim3(8, NN), 256>>>(x);
    k_final<<<dim3(KK, NN), 128>>>(cent, out);
}

// round 7
// speedup vs baseline: 2.6806x; 1.7144x over previous
#include <cuda_runtime.h>
#include <cuda_bf16.h>
#include <math.h>

// NetVLAD: N=32, D=512, S=1600, K=64.
// d_in[0]=x [N,D,S] f32, d_in[1]=W [K,D] f32, d_in[2]=centroids [K,D] f32
// out: [N, K*D] f32

#define NN 32
#define DDIM 512
#define SDIM 1600
#define KK 64
#define NTILES 25   // s-tiles of 64

typedef __nv_bfloat16 bh;

__device__ __align__(16) bh g_a[NN * KK * SDIM];          // a' = softmax*invn (bf16)
__device__ __align__(16) float g_agg2[2][NN * KK * DDIM]; // agg split over 2 s-halves
__device__ __align__(16) float g_asum_part[NN * NTILES * KK];

__device__ __forceinline__ unsigned packbf(float lo, float hi) {
    __nv_bfloat162 h = __floats2bfloat162_rn(lo, hi);
    return *(unsigned*)&h;
}

__device__ __forceinline__ void mma_bf16(float* c, unsigned a0, unsigned a1,
                                         unsigned a2, unsigned a3,
                                         unsigned b0, unsigned b1) {
    asm volatile(
        "mma.sync.aligned.m16n8k16.row.col.f32.bf16.bf16.f32 "
        "{%0,%1,%2,%3},{%4,%5,%6,%7},{%8,%9},{%0,%1,%2,%3};\n"
        : "+f"(c[0]), "+f"(c[1]), "+f"(c[2]), "+f"(c[3])
        : "r"(a0), "r"(a1), "r"(a2), "r"(a3), "r"(b0), "r"(b1));
}

// ---------------------------------------------------------------------------
// Kernel 1: logits = W[64,512] @ x[512, 64 s] (bf16 mma m16n8k16), fused with
// per-pixel sumsq (f32), softmax over k, a_sum partial, a' -> bf16.
// grid (25, 32), 256 threads = 8 warps; warp w: k-rows [(w>>1)*16,+16),
// s-cols [(w&1)*32,+32).
// ---------------------------------------------------------------------------
__global__ __launch_bounds__(256) void k_logits(const float* __restrict__ x,
                                                const float* __restrict__ W) {
    const int n = blockIdx.y;
    const int s0 = blockIdx.x * 64;
    const int tid = threadIdx.x;
    const int warp = tid >> 5, lane = tid & 31;
    const int gid = lane >> 2, tig = lane & 3;
    const int k0 = (warp >> 1) * 16;
    const int sh = (warp & 1) * 32;

    __shared__ __align__(16) char sm[21760];
    // mainloop views (bytes [0, 9728))
    bh (*Wsh)[40]        = (bh(*)[40])sm;                 // 64*40*2 = 5120
    unsigned (*Xint)[72] = (unsigned(*)[72])(sm + 5120);  // 16*72*4 = 4608
    // post-loop views (Lsh aliases mainloop region; rest disjoint)
    float (*Lsh)[65] = (float(*)[65])sm;                  // 64*65*4 = 16640
    float (*ssp)[64] = (float(*)[64])(sm + 16640);        // 8*64*4  = 2048
    float* red1      = (float*)(sm + 18688);              // 4*64*4  = 1024
    float* red2      = (float*)(sm + 19712);              // 1024
    float* sscale    = (float*)(sm + 20736);              // 256
    float* sinv      = (float*)(sm + 20992);              // 256

    float acc[4][4];
#pragma unroll
    for (int j = 0; j < 4; j++)
#pragma unroll
        for (int i = 0; i < 4; i++) acc[j][i] = 0.f;
    float ss[4] = {0.f, 0.f, 0.f, 0.f};

    const float* xb = x + (size_t)n * DDIM * SDIM + s0;
    const int wk = tid >> 2, wc = (tid & 3) * 8;   // W stage: row wk, 8 d
    const int p = tid >> 4, s4 = (tid & 15) * 4;   // x stage: d-pair p, 4 s

    for (int dc = 0; dc < DDIM; dc += 32) {
        float4 w0 = *(const float4*)&W[wk * DDIM + dc + wc];
        float4 w1 = *(const float4*)&W[wk * DDIM + dc + wc + 4];
        uint4 wp;
        wp.x = packbf(w0.x, w0.y); wp.y = packbf(w0.z, w0.w);
        wp.z = packbf(w1.x, w1.y); wp.w = packbf(w1.z, w1.w);
        *(uint4*)&Wsh[wk][wc] = wp;

        const float* xr = &xb[(size_t)(dc + 2 * p) * SDIM + s4];
        float4 x0 = *(const float4*)xr;
        float4 x1 = *(const float4*)(xr + SDIM);
        ss[0] += x0.x * x0.x + x1.x * x1.x;
        ss[1] += x0.y * x0.y + x1.y * x1.y;
        ss[2] += x0.z * x0.z + x1.z * x1.z;
        ss[3] += x0.w * x0.w + x1.w * x1.w;
        uint4 xp;                             // low half = even d (k=2*tig)
        xp.x = packbf(x0.x, x1.x); xp.y = packbf(x0.y, x1.y);
        xp.z = packbf(x0.z, x1.z); xp.w = packbf(x0.w, x1.w);
        *(uint4*)&Xint[p][s4] = xp;
        __syncthreads();

#pragma unroll
        for (int kk2 = 0; kk2 < 16; kk2 += 8) {   // d-offset = 2*kk2
            unsigned a0 = *(unsigned*)&Wsh[k0 + gid][2 * kk2 + 2 * tig];
            unsigned a1 = *(unsigned*)&Wsh[k0 + gid + 8][2 * kk2 + 2 * tig];
            unsigned a2 = *(unsigned*)&Wsh[k0 + gid][2 * kk2 + 2 * tig + 8];
            unsigned a3 = *(unsigned*)&Wsh[k0 + gid + 8][2 * kk2 + 2 * tig + 8];
#pragma unroll
            for (int j = 0; j < 4; j++) {
                unsigned b0 = Xint[kk2 + tig][sh + j * 8 + gid];
                unsigned b1 = Xint[kk2 + tig + 4][sh + j * 8 + gid];
                mma_bf16(acc[j], a0, a1, a2, a3, b0, b1);
            }
        }
        __syncthreads();
    }

    // sumsq: fold lane<->lane+16 (p, p+1), then per-warp partials to smem
#pragma unroll
    for (int i = 0; i < 4; i++) ss[i] += __shfl_xor_sync(0xffffffffu, ss[i], 16);
    if (lane < 16)
        *(float4*)&ssp[warp][lane * 4] = make_float4(ss[0], ss[1], ss[2], ss[3]);

    // logits -> Lsh (aliases Wsh/Xint; safe past the final barrier)
#pragma unroll
    for (int j = 0; j < 4; j++) {
        Lsh[k0 + gid][sh + j * 8 + 2 * tig]         = acc[j][0];
        Lsh[k0 + gid][sh + j * 8 + 2 * tig + 1]     = acc[j][1];
        Lsh[k0 + gid + 8][sh + j * 8 + 2 * tig]     = acc[j][2];
        Lsh[k0 + gid + 8][sh + j * 8 + 2 * tig + 1] = acc[j][3];
    }
    __syncthreads();

    // softmax: 4 threads per pixel (q = k-quarter), s = pixel
    const int q = tid >> 6, s = tid & 63;
    float tot = 0.f;
#pragma unroll
    for (int w = 0; w < 8; w++) tot += ssp[w][s];
    const float sc = 1.f / fmaxf(sqrtf(tot), 1e-12f);

    float m = -1e30f;
#pragma unroll
    for (int kq = 0; kq < 16; kq++) m = fmaxf(m, Lsh[q * 16 + kq][s] * sc);
    red1[q * 64 + s] = m;
    __syncthreads();
    m = fmaxf(fmaxf(red1[s], red1[64 + s]), fmaxf(red1[128 + s], red1[192 + s]));

    float sump = 0.f;
#pragma unroll
    for (int kq = 0; kq < 16; kq++) {
        float e = __expf(Lsh[q * 16 + kq][s] * sc - m);
        Lsh[q * 16 + kq][s] = e;
        sump += e;
    }
    red2[q * 64 + s] = sump;
    __syncthreads();
    if (q == 0) {
        float sum = red2[s] + red2[64 + s] + red2[128 + s] + red2[192 + s];
        sscale[s] = sc;
        sinv[s] = 1.f / sum;
    }
    __syncthreads();

    // a_sum partial: 4 threads per k, each sums 16 pixels
    {
        const int k = tid & 63;
        float t = 0.f;
#pragma unroll
        for (int sq = 0; sq < 16; sq++) {
            int sp = q * 16 + sq;
            t += Lsh[k][sp] * sinv[sp];
        }
        red1[q * 64 + k] = t;
    }
    __syncthreads();
    if (tid < 64)
        g_asum_part[((size_t)n * NTILES + blockIdx.x) * KK + tid] =
            red1[tid] + red1[64 + tid] + red1[128 + tid] + red1[192 + tid];

    // a' = softmax * invn -> bf16 pairs (u32 stores, coalesced over s)
    unsigned* ab32 = (unsigned*)g_a + (size_t)n * KK * (SDIM / 2) + (s0 >> 1);
#pragma unroll
    for (int i = 0; i < 8; i++) {
        int idx = tid + i * 256;
        int k = idx >> 5, s2 = (idx & 31) * 2;
        float v0 = Lsh[k][s2] * sinv[s2] * sscale[s2];
        float v1 = Lsh[k][s2 + 1] * sinv[s2 + 1] * sscale[s2 + 1];
        ab32[(size_t)k * (SDIM / 2) + (s2 >> 1)] = packbf(v0, v1);
    }
}

// ---------------------------------------------------------------------------
// Kernel 2: agg[d,k] += sum_s x[d,s]*a'[k,s]  (bf16 mma; A=x d-rows, B=a').
// grid (8 d-tiles, 32 n, 2 s-halves), 256 threads = 8 warps.
// Warp w: d-rows [(w>>1)*16,+16), k-cols [(w&1)*32,+32). No transpose needed
// for B: a' is [k][s] with s contiguous = col-major fragment layout.
// ---------------------------------------------------------------------------
__global__ __launch_bounds__(256) void k_agg(const float* __restrict__ x) {
    const int n = blockIdx.y;
    const int d0 = blockIdx.x * 64;
    const int h = blockIdx.z;          // s-half
    const int tid = threadIdx.x;
    const int warp = tid >> 5, lane = tid & 31;
    const int gid = lane >> 2, tig = lane & 3;
    const int dw0 = (warp >> 1) * 16;
    const int kh = (warp & 1) * 32;

    __shared__ __align__(16) char sm[17408];
    bh (*Xs)[40] = (bh(*)[40])sm;            // 64*40*2 = 5120  (x tile, d rows)
    bh (*As)[40] = (bh(*)[40])(sm + 5120);   // 64*40*2 = 5120  (a' tile, k rows)
    float (*Tsh)[68] = (float(*)[68])sm;     // 64*68*4 = 17408 (post-loop alias)

    float acc[4][4];
#pragma unroll
    for (int j = 0; j < 4; j++)
#pragma unroll
        for (int i = 0; i < 4; i++) acc[j][i] = 0.f;

    const float* xb = x + (size_t)n * DDIM * SDIM + (size_t)d0 * SDIM;
    const unsigned* ag = (const unsigned*)g_a + (size_t)n * KK * (SDIM / 2);
    const int r = tid >> 2, s8 = (tid & 3) * 8;
    const int sbase = h * (SDIM / 2);

    for (int c = 0; c < 25; c++) {
        const int scg = sbase + c * 32;
        const float* xr = &xb[(size_t)r * SDIM + scg + s8];
        float4 x0 = *(const float4*)xr;
        float4 x1 = *(const float4*)(xr + 4);
        uint4 xp;                             // low half = even s
        xp.x = packbf(x0.x, x0.y); xp.y = packbf(x0.z, x0.w);
        xp.z = packbf(x1.x, x1.y); xp.w = packbf(x1.z, x1.w);
        *(uint4*)&Xs[r][s8] = xp;
        uint4 ap = *(const uint4*)&ag[(size_t)r * (SDIM / 2) + ((scg + s8) >> 1)];
        *(uint4*)&As[r][s8] = ap;
        __syncthreads();

#pragma unroll
        for (int kk2 = 0; kk2 < 16; kk2 += 8) {   // s-offset = 2*kk2
            unsigned a0 = *(unsigned*)&Xs[dw0 + gid][2 * kk2 + 2 * tig];
            unsigned a1 = *(unsigned*)&Xs[dw0 + gid + 8][2 * kk2 + 2 * tig];
            unsigned a2 = *(unsigned*)&Xs[dw0 + gid][2 * kk2 + 2 * tig + 8];
            unsigned a3 = *(unsigned*)&Xs[dw0 + gid + 8][2 * kk2 + 2 * tig + 8];
#pragma unroll
            for (int j = 0; j < 4; j++) {
                unsigned b0 = *(unsigned*)&As[kh + j * 8 + gid][2 * kk2 + 2 * tig];
                unsigned b1 = *(unsigned*)&As[kh + j * 8 + gid][2 * kk2 + 2 * tig + 8];
                mma_bf16(acc[j], a0, a1, a2, a3, b0, b1);
            }
        }
        __syncthreads();
    }

    // transpose: C[d = dw0+gid(+8)][k = kh+8j+2tig(+1)] -> Tsh[k][d]
#pragma unroll
    for (int j = 0; j < 4; j++) {
        Tsh[kh + j * 8 + 2 * tig][dw0 + gid]         = acc[j][0];
        Tsh[kh + j * 8 + 2 * tig + 1][dw0 + gid]     = acc[j][1];
        Tsh[kh + j * 8 + 2 * tig][dw0 + gid + 8]     = acc[j][2];
        Tsh[kh + j * 8 + 2 * tig + 1][dw0 + gid + 8] = acc[j][3];
    }
    __syncthreads();
    float* dst = &g_agg2[h][(size_t)n * KK * DDIM + d0];
#pragma unroll
    for (int i = 0; i < 4; i++) {
        int idx = tid + i * 256;
        int k = idx >> 4, dd4 = (idx & 15) * 4;
        *(float4*)&dst[(size_t)k * DDIM + dd4] = *(const float4*)&Tsh[k][dd4];
    }
}

// ---------------------------------------------------------------------------
// Kernel 3: a_sum reduce; vlad = (agg0+agg1) - a_sum*c; intra-norm over D;
// *1/8 (global norm of 64 unit rows is exactly 8). grid (64,32), 128 thr.
// ---------------------------------------------------------------------------
__global__ __launch_bounds__(128) void k_final(const float* __restrict__ cent,
                                               float* __restrict__ out) {
    const int k = blockIdx.x, n = blockIdx.y;
    const int tid = threadIdx.x;

    __shared__ float s_as;
    __shared__ float wpart[4];

    if (tid < 32) {
        float p = (tid < NTILES)
                      ? g_asum_part[((size_t)n * NTILES + tid) * KK + k]
                      : 0.f;
#pragma unroll
        for (int o = 16; o > 0; o >>= 1) p += __shfl_xor_sync(0xffffffffu, p, o);
        if (tid == 0) s_as = p;
    }
    __syncthreads();
    const float as = s_as;

    const size_t base = ((size_t)n * KK + k) * DDIM + tid * 4;
    float4 a0 = *(const float4*)&g_agg2[0][base];
    float4 a1 = *(const float4*)&g_agg2[1][base];
    float4 c4 = *(const float4*)&cent[(size_t)k * DDIM + tid * 4];
    float vx = a0.x + a1.x - as * c4.x;
    float vy = a0.y + a1.y - as * c4.y;
    float vz = a0.z + a1.z - as * c4.z;
    float vw = a0.w + a1.w - as * c4.w;
    float ss = vx * vx + vy * vy + vz * vz + vw * vw;

#pragma unroll
    for (int o = 16; o > 0; o >>= 1) ss += __shfl_xor_sync(0xffffffffu, ss, o);
    if ((tid & 31) == 0) wpart[tid >> 5] = ss;
    __syncthreads();
    float tot = wpart[0] + wpart[1] + wpart[2] + wpart[3];

    const float inv = 0.125f / fmaxf(sqrtf(tot), 1e-12f);
    float4 o4 = make_float4(vx * inv, vy * inv, vz * inv, vw * inv);
    *(float4*)&out[(size_t)n * (KK * DDIM) + (size_t)k * DDIM + tid * 4] = o4;
}

extern "C" void kernel_launch(void* const* d_in, const int* in_sizes, int n_in,
                              void* d_out, int out_size) {
    const float* x    = (const float*)d_in[0];
    const float* W    = (const float*)d_in[1];
    const float* cent = (const float*)d_in[2];
    float* out = (float*)d_out;

    k_logits<<<dim3(NTILES, NN), 256>>>(x, W);
    k_agg<<<dim3(8, NN, 2), 256>>>(x);
    k_final<<<dim3(KK, NN), 128>>>(cent, out);
}

// round 10
// speedup vs baseline: 3.2086x; 1.1970x over previous
#include <cuda_runtime.h>
#include <cuda_bf16.h>
#include <math.h>

// NetVLAD: N=32, D=512, S=1600, K=64.
// d_in[0]=x [N,D,S] f32, d_in[1]=W [K,D] f32, d_in[2]=centroids [K,D] f32
// out: [N, K*D] f32

#define NN 32
#define DDIM 512
#define SDIM 1600
#define KK 64
#define NTILES 25   // s-tiles of 64

typedef __nv_bfloat16 bh;

__device__ __align__(16) bh g_a[NN * KK * SDIM];          // a' = softmax*invn (bf16)
__device__ __align__(16) float g_agg2[2][NN * KK * DDIM]; // agg split over 2 s-halves
__device__ __align__(16) float g_asum_part[NN * NTILES * KK];

__device__ __forceinline__ unsigned packbf(float lo, float hi) {
    __nv_bfloat162 h = __floats2bfloat162_rn(lo, hi);
    return *(unsigned*)&h;
}

__device__ __forceinline__ void mma_bf16(float* c, unsigned a0, unsigned a1,
                                         unsigned a2, unsigned a3,
                                         unsigned b0, unsigned b1) {
    asm volatile(
        "mma.sync.aligned.m16n8k16.row.col.f32.bf16.bf16.f32 "
        "{%0,%1,%2,%3},{%4,%5,%6,%7},{%8,%9},{%0,%1,%2,%3};\n"
        : "+f"(c[0]), "+f"(c[1]), "+f"(c[2]), "+f"(c[3])
        : "r"(a0), "r"(a1), "r"(a2), "r"(a3), "r"(b0), "r"(b1));
}

// ---------------------------------------------------------------------------
// Kernel 1: logits = W[64,512] @ x[512, 64 s] (bf16 mma m16n8k16), software-
// pipelined (double-buffered smem, 1 bar/chunk), fused with per-pixel sumsq,
// softmax over k, a_sum partial, a' -> bf16.
// grid (25, 32), 256 threads = 8 warps; warp w: k-rows [(w>>1)*16,+16),
// s-cols [(w&1)*32,+32).
// ---------------------------------------------------------------------------
__global__ __launch_bounds__(256) void k_logits(const float* __restrict__ x,
                                                const float* __restrict__ W) {
    const int n = blockIdx.y;
    const int s0 = blockIdx.x * 64;
    const int tid = threadIdx.x;
    const int warp = tid >> 5, lane = tid & 31;
    const int gid = lane >> 2, tig = lane & 3;
    const int k0 = (warp >> 1) * 16;
    const int sh = (warp & 1) * 32;

    __shared__ __align__(16) char sm[21248];
    // mainloop double buffers
    bh (*Wb0)[40]      = (bh(*)[40])(sm);              // 5120
    bh (*Wb1)[40]      = (bh(*)[40])(sm + 5120);       // 5120
    unsigned (*Xb0)[72] = (unsigned(*)[72])(sm + 10240); // 4608
    unsigned (*Xb1)[72] = (unsigned(*)[72])(sm + 14848); // 4608 -> 19456
    // post-loop views (alias mainloop region; used only after final barrier)
    float (*Lsh)[65] = (float(*)[65])sm;               // 16640
    float (*ssp)[64] = (float(*)[64])(sm + 16640);     // 2048
    float* red1      = (float*)(sm + 18688);           // 1024
    float* red2      = (float*)(sm + 19712);           // 1024
    float* sscale    = (float*)(sm + 20736);           // 256
    float* sinv      = (float*)(sm + 20992);           // 256

    float acc[4][4];
#pragma unroll
    for (int j = 0; j < 4; j++)
#pragma unroll
        for (int i = 0; i < 4; i++) acc[j][i] = 0.f;
    float ss[4] = {0.f, 0.f, 0.f, 0.f};

    const float* xb = x + (size_t)n * DDIM * SDIM + s0;
    const int wk = tid >> 2, wc = (tid & 3) * 8;   // W stage: row wk, 8 d
    const int p = tid >> 4, s4 = (tid & 15) * 4;   // x stage: d-pair p, 4 s

    // ---- prologue: stage chunk 0 into buffer 0 ----
    {
        float4 w0 = *(const float4*)&W[wk * DDIM + wc];
        float4 w1 = *(const float4*)&W[wk * DDIM + wc + 4];
        uint4 wp;
        wp.x = packbf(w0.x, w0.y); wp.y = packbf(w0.z, w0.w);
        wp.z = packbf(w1.x, w1.y); wp.w = packbf(w1.z, w1.w);
        *(uint4*)&Wb0[wk][wc] = wp;
        const float* xr = &xb[(size_t)(2 * p) * SDIM + s4];
        float4 x0 = *(const float4*)xr;
        float4 x1 = *(const float4*)(xr + SDIM);
        ss[0] += x0.x * x0.x + x1.x * x1.x;
        ss[1] += x0.y * x0.y + x1.y * x1.y;
        ss[2] += x0.z * x0.z + x1.z * x1.z;
        ss[3] += x0.w * x0.w + x1.w * x1.w;
        uint4 xp;                             // low half = even d
        xp.x = packbf(x0.x, x1.x); xp.y = packbf(x0.y, x1.y);
        xp.z = packbf(x0.z, x1.z); xp.w = packbf(x0.w, x1.w);
        *(uint4*)&Xb0[p][s4] = xp;
    }
    __syncthreads();

#pragma unroll 2
    for (int c = 0; c < 16; c++) {
        bh (*Wc)[40]        = (c & 1) ? Wb1 : Wb0;
        unsigned (*Xc)[72]  = (c & 1) ? Xb1 : Xb0;
        bh (*Wn)[40]        = (c & 1) ? Wb0 : Wb1;
        unsigned (*Xn)[72]  = (c & 1) ? Xb0 : Xb1;

        // issue next chunk's loads before compute (overlap with mma)
        float4 nw0, nw1, nx0, nx1;
        if (c < 15) {
            const int dc = (c + 1) * 32;
            nw0 = *(const float4*)&W[wk * DDIM + dc + wc];
            nw1 = *(const float4*)&W[wk * DDIM + dc + wc + 4];
            const float* xr = &xb[(size_t)(dc + 2 * p) * SDIM + s4];
            nx0 = *(const float4*)xr;
            nx1 = *(const float4*)(xr + SDIM);
        }

#pragma unroll
        for (int kk2 = 0; kk2 < 16; kk2 += 8) {   // d-offset = 2*kk2
            unsigned a0 = *(unsigned*)&Wc[k0 + gid][2 * kk2 + 2 * tig];
            unsigned a1 = *(unsigned*)&Wc[k0 + gid + 8][2 * kk2 + 2 * tig];
            unsigned a2 = *(unsigned*)&Wc[k0 + gid][2 * kk2 + 2 * tig + 8];
            unsigned a3 = *(unsigned*)&Wc[k0 + gid + 8][2 * kk2 + 2 * tig + 8];
#pragma unroll
            for (int j = 0; j < 4; j++) {
                unsigned b0 = Xc[kk2 + tig][sh + j * 8 + gid];
                unsigned b1 = Xc[kk2 + tig + 4][sh + j * 8 + gid];
                mma_bf16(acc[j], a0, a1, a2, a3, b0, b1);
            }
        }

        if (c < 15) {
            ss[0] += nx0.x * nx0.x + nx1.x * nx1.x;
            ss[1] += nx0.y * nx0.y + nx1.y * nx1.y;
            ss[2] += nx0.z * nx0.z + nx1.z * nx1.z;
            ss[3] += nx0.w * nx0.w + nx1.w * nx1.w;
            uint4 wp;
            wp.x = packbf(nw0.x, nw0.y); wp.y = packbf(nw0.z, nw0.w);
            wp.z = packbf(nw1.x, nw1.y); wp.w = packbf(nw1.z, nw1.w);
            *(uint4*)&Wn[wk][wc] = wp;
            uint4 xp;
            xp.x = packbf(nx0.x, nx1.x); xp.y = packbf(nx0.y, nx1.y);
            xp.z = packbf(nx0.z, nx1.z); xp.w = packbf(nx0.w, nx1.w);
            *(uint4*)&Xn[p][s4] = xp;
        }
        __syncthreads();
    }

    // sumsq: fold lane<->lane+16 (rows 2p / 2p+1), per-warp partials to smem
#pragma unroll
    for (int i = 0; i < 4; i++) ss[i] += __shfl_xor_sync(0xffffffffu, ss[i], 16);
    if (lane < 16)
        *(float4*)&ssp[warp][lane * 4] = make_float4(ss[0], ss[1], ss[2], ss[3]);

    // logits -> Lsh (aliases mainloop buffers; reads are all done)
#pragma unroll
    for (int j = 0; j < 4; j++) {
        Lsh[k0 + gid][sh + j * 8 + 2 * tig]         = acc[j][0];
        Lsh[k0 + gid][sh + j * 8 + 2 * tig + 1]     = acc[j][1];
        Lsh[k0 + gid + 8][sh + j * 8 + 2 * tig]     = acc[j][2];
        Lsh[k0 + gid + 8][sh + j * 8 + 2 * tig + 1] = acc[j][3];
    }
    __syncthreads();

    // softmax: 4 threads per pixel (q = k-quarter), s = pixel
    const int q = tid >> 6, s = tid & 63;
    float tot = 0.f;
#pragma unroll
    for (int w = 0; w < 8; w++) tot += ssp[w][s];
    const float sc = 1.f / fmaxf(sqrtf(tot), 1e-12f);

    float m = -1e30f;
#pragma unroll
    for (int kq = 0; kq < 16; kq++) m = fmaxf(m, Lsh[q * 16 + kq][s] * sc);
    red1[q * 64 + s] = m;
    __syncthreads();
    m = fmaxf(fmaxf(red1[s], red1[64 + s]), fmaxf(red1[128 + s], red1[192 + s]));

    float sump = 0.f;
#pragma unroll
    for (int kq = 0; kq < 16; kq++) {
        float e = __expf(Lsh[q * 16 + kq][s] * sc - m);
        Lsh[q * 16 + kq][s] = e;
        sump += e;
    }
    red2[q * 64 + s] = sump;
    __syncthreads();
    if (q == 0) {
        float sum = red2[s] + red2[64 + s] + red2[128 + s] + red2[192 + s];
        sscale[s] = sc;
        sinv[s] = 1.f / sum;
    }
    __syncthreads();

    // a_sum partial: 4 threads per k, each sums 16 pixels
    {
        const int k = tid & 63;
        float t = 0.f;
#pragma unroll
        for (int sq = 0; sq < 16; sq++) {
            int sp = q * 16 + sq;
            t += Lsh[k][sp] * sinv[sp];
        }
        red1[q * 64 + k] = t;
    }
    __syncthreads();
    if (tid < 64)
        g_asum_part[((size_t)n * NTILES + blockIdx.x) * KK + tid] =
            red1[tid] + red1[64 + tid] + red1[128 + tid] + red1[192 + tid];

    // a' = softmax * invn -> bf16 pairs (u32 stores, coalesced over s)
    unsigned* ab32 = (unsigned*)g_a + (size_t)n * KK * (SDIM / 2) + (s0 >> 1);
#pragma unroll
    for (int i = 0; i < 8; i++) {
        int idx = tid + i * 256;
        int k = idx >> 5, s2 = (idx & 31) * 2;
        float v0 = Lsh[k][s2] * sinv[s2] * sscale[s2];
        float v1 = Lsh[k][s2 + 1] * sinv[s2 + 1] * sscale[s2 + 1];
        ab32[(size_t)k * (SDIM / 2) + (s2 >> 1)] = packbf(v0, v1);
    }
}

// ---------------------------------------------------------------------------
// Kernel 2: agg[d,k] += sum_s x[d,s]*a'[k,s]  (bf16 mma; A=x d-rows, B=a'),
// software-pipelined (double-buffered smem, 1 bar/chunk).
// grid (8 d-tiles, 32 n, 2 s-halves), 256 threads = 8 warps.
// Warp w: d-rows [(w>>1)*16,+16), k-cols [(w&1)*32,+32).
// ---------------------------------------------------------------------------
__global__ __launch_bounds__(256) void k_agg(const float* __restrict__ x) {
    const int n = blockIdx.y;
    const int d0 = blockIdx.x * 64;
    const int h = blockIdx.z;          // s-half
    const int tid = threadIdx.x;
    const int warp = tid >> 5, lane = tid & 31;
    const int gid = lane >> 2, tig = lane & 3;
    const int dw0 = (warp >> 1) * 16;
    const int kh = (warp & 1) * 32;

    __shared__ __align__(16) char sm[20480];
    bh (*Xs0)[40] = (bh(*)[40])(sm);            // 5120
    bh (*Xs1)[40] = (bh(*)[40])(sm + 5120);     // 5120
    bh (*As0)[40] = (bh(*)[40])(sm + 10240);    // 5120
    bh (*As1)[40] = (bh(*)[40])(sm + 15360);    // 5120
    float (*Tsh)[68] = (float(*)[68])sm;        // 17408 (post-loop alias)

    float acc[4][4];
#pragma unroll
    for (int j = 0; j < 4; j++)
#pragma unroll
        for (int i = 0; i < 4; i++) acc[j][i] = 0.f;

    const float* xb = x + (size_t)n * DDIM * SDIM + (size_t)d0 * SDIM;
    const unsigned* ag = (const unsigned*)g_a + (size_t)n * KK * (SDIM / 2);
    const int r = tid >> 2, s8 = (tid & 3) * 8;
    const int sbase = h * (SDIM / 2);

    // ---- prologue: stage chunk 0 into buffer 0 ----
    {
        const float* xr = &xb[(size_t)r * SDIM + sbase + s8];
        float4 x0 = *(const float4*)xr;
        float4 x1 = *(const float4*)(xr + 4);
        uint4 xp;                             // low half = even s
        xp.x = packbf(x0.x, x0.y); xp.y = packbf(x0.z, x0.w);
        xp.z = packbf(x1.x, x1.y); xp.w = packbf(x1.z, x1.w);
        *(uint4*)&Xs0[r][s8] = xp;
        *(uint4*)&As0[r][s8] =
            *(const uint4*)&ag[(size_t)r * (SDIM / 2) + ((sbase + s8) >> 1)];
    }
    __syncthreads();

#pragma unroll 2
    for (int c = 0; c < 25; c++) {
        bh (*Xc)[40] = (c & 1) ? Xs1 : Xs0;
        bh (*Ac)[40] = (c & 1) ? As1 : As0;
        bh (*Xn)[40] = (c & 1) ? Xs0 : Xs1;
        bh (*An)[40] = (c & 1) ? As0 : As1;

        float4 nx0, nx1; uint4 nap;
        if (c < 24) {
            const int scg = sbase + (c + 1) * 32;
            const float* xr = &xb[(size_t)r * SDIM + scg + s8];
            nx0 = *(const float4*)xr;
            nx1 = *(const float4*)(xr + 4);
            nap = *(const uint4*)&ag[(size_t)r * (SDIM / 2) + ((scg + s8) >> 1)];
        }

#pragma unroll
        for (int kk2 = 0; kk2 < 16; kk2 += 8) {   // s-offset = 2*kk2
            unsigned a0 = *(unsigned*)&Xc[dw0 + gid][2 * kk2 + 2 * tig];
            unsigned a1 = *(unsigned*)&Xc[dw0 + gid + 8][2 * kk2 + 2 * tig];
            unsigned a2 = *(unsigned*)&Xc[dw0 + gid][2 * kk2 + 2 * tig + 8];
            unsigned a3 = *(unsigned*)&Xc[dw0 + gid + 8][2 * kk2 + 2 * tig + 8];
#pragma unroll
            for (int j = 0; j < 4; j++) {
                unsigned b0 = *(unsigned*)&Ac[kh + j * 8 + gid][2 * kk2 + 2 * tig];
                unsigned b1 = *(unsigned*)&Ac[kh + j * 8 + gid][2 * kk2 + 2 * tig + 8];
                mma_bf16(acc[j], a0, a1, a2, a3, b0, b1);
            }
        }

        if (c < 24) {
            uint4 xp;
            xp.x = packbf(nx0.x, nx0.y); xp.y = packbf(nx0.z, nx0.w);
            xp.z = packbf(nx1.x, nx1.y); xp.w = packbf(nx1.z, nx1.w);
            *(uint4*)&Xn[r][s8] = xp;
            *(uint4*)&An[r][s8] = nap;
        }
        __syncthreads();
    }

    // transpose: C[d = dw0+gid(+8)][k = kh+8j+2tig(+1)] -> Tsh[k][d]
#pragma unroll
    for (int j = 0; j < 4; j++) {
        Tsh[kh + j * 8 + 2 * tig][dw0 + gid]         = acc[j][0];
        Tsh[kh + j * 8 + 2 * tig + 1][dw0 + gid]     = acc[j][1];
        Tsh[kh + j * 8 + 2 * tig][dw0 + gid + 8]     = acc[j][2];
        Tsh[kh + j * 8 + 2 * tig + 1][dw0 + gid + 8] = acc[j][3];
    }
    __syncthreads();
    float* dst = &g_agg2[h][(size_t)n * KK * DDIM + d0];
#pragma unroll
    for (int i = 0; i < 4; i++) {
        int idx = tid + i * 256;
        int k = idx >> 4, dd4 = (idx & 15) * 4;
        *(float4*)&dst[(size_t)k * DDIM + dd4] = *(const float4*)&Tsh[k][dd4];
    }
}

// ---------------------------------------------------------------------------
// Kernel 3: a_sum reduce; vlad = (agg0+agg1) - a_sum*c; intra-norm over D;
// *1/8 (global norm of 64 unit rows is exactly 8). grid (64,32), 128 thr.
// ---------------------------------------------------------------------------
__global__ __launch_bounds__(128) void k_final(const float* __restrict__ cent,
                                               float* __restrict__ out) {
    const int k = blockIdx.x, n = blockIdx.y;
    const int tid = threadIdx.x;

    __shared__ float s_as;
    __shared__ float wpart[4];

    if (tid < 32) {
        float p = (tid < NTILES)
                      ? g_asum_part[((size_t)n * NTILES + tid) * KK + k]
                      : 0.f;
#pragma unroll
        for (int o = 16; o > 0; o >>= 1) p += __shfl_xor_sync(0xffffffffu, p, o);
        if (tid == 0) s_as = p;
    }
    __syncthreads();
    const float as = s_as;

    const size_t base = ((size_t)n * KK + k) * DDIM + tid * 4;
    float4 a0 = *(const float4*)&g_agg2[0][base];
    float4 a1 = *(const float4*)&g_agg2[1][base];
    float4 c4 = *(const float4*)&cent[(size_t)k * DDIM + tid * 4];
    float vx = a0.x + a1.x - as * c4.x;
    float vy = a0.y + a1.y - as * c4.y;
    float vz = a0.z + a1.z - as * c4.z;
    float vw = a0.w + a1.w - as * c4.w;
    float ss = vx * vx + vy * vy + vz * vz + vw * vw;

#pragma unroll
    for (int o = 16; o > 0; o >>= 1) ss += __shfl_xor_sync(0xffffffffu, ss, o);
    if ((tid & 31) == 0) wpart[tid >> 5] = ss;
    __syncthreads();
    float tot = wpart[0] + wpart[1] + wpart[2] + wpart[3];

    const float inv = 0.125f / fmaxf(sqrtf(tot), 1e-12f);
    float4 o4 = make_float4(vx * inv, vy * inv, vz * inv, vw * inv);
    *(float4*)&out[(size_t)n * (KK * DDIM) + (size_t)k * DDIM + tid * 4] = o4;
}

extern "C" void kernel_launch(void* const* d_in, const int* in_sizes, int n_in,
                              void* d_out, int out_size) {
    const float* x    = (const float*)d_in[0];
    const float* W    = (const float*)d_in[1];
    const float* cent = (const float*)d_in[2];
    float* out = (float*)d_out;

    k_logits<<<dim3(NTILES, NN), 256>>>(x, W);
    k_agg<<<dim3(8, NN, 2), 256>>>(x);
    k_final<<<dim3(KK, NN), 128>>>(cent, out);
}